// round 2
// baseline (speedup 1.0000x reference)
#include <cuda_runtime.h>
#include <cstddef>

#define N_NODES 100000
#define N_EDGES 1600000
#define F_IN    128
#define HID     150
#define HID_PAD 160
#define N_OUT   128
#define W1_ROWS 256   // 128 self + 128 neigh
#define W1_COLS 192   // 150 padded to 3*64

// ---------------- scratch (static device globals; zero-initialized) ----------
__device__ float g_deg[N_NODES];
__device__ float g_deginv[N_NODES];
__device__ float g_agg1[(size_t)N_NODES * F_IN];
__device__ float g_agg2[(size_t)N_NODES * N_OUT];
__device__ float g_h1[(size_t)N_NODES * HID_PAD];   // cols 150..159 stay 0 forever
__device__ float g_t2[(size_t)N_NODES * N_OUT];
__device__ float g_W1cat[W1_ROWS * W1_COLS];
__device__ float g_W2s[HID_PAD * N_OUT];
__device__ float g_W2n[HID_PAD * N_OUT];

// ---------------- small utility kernels --------------------------------------
__global__ void zero_f4(float4* p, size_t n4) {
    size_t i = (size_t)blockIdx.x * blockDim.x + threadIdx.x;
    size_t stride = (size_t)gridDim.x * blockDim.x;
    float4 z = make_float4(0.f, 0.f, 0.f, 0.f);
    for (; i < n4; i += stride) p[i] = z;
}

__global__ void prep_weights(const float* __restrict__ Ws1,
                             const float* __restrict__ Wn1,
                             const float* __restrict__ Ws2,
                             const float* __restrict__ Wn2) {
    int i = blockIdx.x * blockDim.x + threadIdx.x;
    if (i < W1_ROWS * W1_COLS) {
        int k = i / W1_COLS, n = i % W1_COLS;
        float v = 0.f;
        if (n < HID) v = (k < F_IN) ? Ws1[k * HID + n] : Wn1[(k - F_IN) * HID + n];
        g_W1cat[i] = v;
    }
    if (i < HID_PAD * N_OUT) {
        int k = i / N_OUT, n = i % N_OUT;
        g_W2s[i] = (k < HID) ? Ws2[k * N_OUT + n] : 0.f;
        g_W2n[i] = (k < HID) ? Wn2[k * N_OUT + n] : 0.f;
    }
}

__global__ void deg_kernel(const int* __restrict__ dst) {
    int e = blockIdx.x * blockDim.x + threadIdx.x;
    if (e < N_EDGES) atomicAdd(&g_deg[dst[e]], 1.0f);
}

__global__ void deginv_kernel() {
    int i = blockIdx.x * blockDim.x + threadIdx.x;
    if (i < N_NODES) {
        float d = g_deg[i];
        g_deginv[i] = (d > 0.f) ? (1.0f / d) : 0.f;
    }
}

// one warp per edge; 32 lanes * float4 = 128 features
__global__ void scatter128(const float* __restrict__ feat,
                           const int* __restrict__ src,
                           const int* __restrict__ dst,
                           float* __restrict__ out) {
    long long gid = (long long)blockIdx.x * blockDim.x + threadIdx.x;
    int e = (int)(gid >> 5);
    int lane = (int)(gid & 31);
    if (e >= N_EDGES) return;
    int s = __ldg(&src[e]);
    int d = __ldg(&dst[e]);
    float4 v = ((const float4*)feat)[(size_t)s * 32 + lane];
    float* p = out + (size_t)d * 128 + lane * 4;
    asm volatile("red.global.add.v4.f32 [%0], {%1, %2, %3, %4};"
                 :: "l"(p), "f"(v.x), "f"(v.y), "f"(v.z), "f"(v.w) : "memory");
}

// ---------------- fused GEMM ---------------------------------------------------
// MODE 1: C = relu([A | deginv*A2] @ W + bias)       A=x(lda 128), A2=agg1, K=256
// MODE 2: C = A @ W                                  A=h1(lda 160), K=160
// MODE 3: C = A @ W + bias + deginv[row]*addin[row,col]
template <int MODE>
__global__ void __launch_bounds__(256)
gemm_kernel(const float* __restrict__ A,
            const float* __restrict__ A2,
            const float* __restrict__ W,
            const float* __restrict__ bias,
            const float* __restrict__ addin,
            float* __restrict__ C,
            int M, int Nstore, int K, int lda, int ldw, int ldc) {
    __shared__ float As[16][68];
    __shared__ float Bs[16][64];
    __shared__ float dvs[64];

    int tid = threadIdx.x;
    int row0 = blockIdx.y * 64;
    int n0 = blockIdx.x * 64;

    if (MODE == 1 || MODE == 3) {
        if (tid < 64) {
            int r = row0 + tid;
            dvs[tid] = (r < M) ? g_deginv[r] : 0.f;
        }
    }

    int ty = tid >> 4, tx = tid & 15;
    int am = tid >> 2;           // 0..63 (row within tile)
    int ak = (tid & 3) * 4;      // 0,4,8,12
    int bk = tid >> 4;           // 0..15
    int bn = (tid & 15) * 4;     // 0..60

    float acc[4][4];
#pragma unroll
    for (int i = 0; i < 4; i++)
#pragma unroll
        for (int j = 0; j < 4; j++) acc[i][j] = 0.f;

    for (int k0 = 0; k0 < K; k0 += 16) {
        // global loads into registers
        float4 av = make_float4(0.f, 0.f, 0.f, 0.f);
        int row = row0 + am;
        if (row < M) {
            if (MODE == 1) {
                if (k0 < 128) {
                    av = *(const float4*)&A[(size_t)row * 128 + k0 + ak];
                } else {
                    av = *(const float4*)&A2[(size_t)row * 128 + (k0 - 128) + ak];
                }
            } else {
                av = *(const float4*)&A[(size_t)row * lda + k0 + ak];
            }
        }
        float4 bv = *(const float4*)&W[(size_t)(k0 + bk) * ldw + n0 + bn];

        __syncthreads();   // previous compute done (also guards dvs on 1st iter)
        if (MODE == 1 && k0 >= 128) {
            float dv = dvs[am];
            av.x *= dv; av.y *= dv; av.z *= dv; av.w *= dv;
        }
        As[ak + 0][am] = av.x;
        As[ak + 1][am] = av.y;
        As[ak + 2][am] = av.z;
        As[ak + 3][am] = av.w;
        *(float4*)&Bs[bk][bn] = bv;
        __syncthreads();

#pragma unroll
        for (int kk = 0; kk < 16; kk++) {
            float4 a = *(const float4*)&As[kk][ty * 4];
            float4 b = *(const float4*)&Bs[kk][tx * 4];
            float ar[4] = {a.x, a.y, a.z, a.w};
            float br[4] = {b.x, b.y, b.z, b.w};
#pragma unroll
            for (int i = 0; i < 4; i++)
#pragma unroll
                for (int j = 0; j < 4; j++)
                    acc[i][j] = fmaf(ar[i], br[j], acc[i][j]);
        }
    }

    // epilogue
#pragma unroll
    for (int i = 0; i < 4; i++) {
        int row = row0 + ty * 4 + i;
        if (row >= M) continue;
#pragma unroll
        for (int j = 0; j < 4; j++) {
            int col = n0 + tx * 4 + j;
            if (col >= Nstore) continue;
            float v = acc[i][j];
            if (MODE == 1) {
                v += bias[col];
                v = fmaxf(v, 0.f);
            }
            if (MODE == 3) {
                v += bias[col] + dvs[ty * 4 + i] * addin[(size_t)row * 128 + col];
            }
            C[(size_t)row * ldc + col] = v;
        }
    }
}

// ---------------- launch --------------------------------------------------------
extern "C" void kernel_launch(void* const* d_in, const int* in_sizes, int n_in,
                              void* d_out, int out_size) {
    const float* x   = (const float*)d_in[0];
    const int*   src = (const int*)d_in[1];
    const int*   dst = (const int*)d_in[2];
    const float* Ws1 = (const float*)d_in[3];
    const float* Wn1 = (const float*)d_in[4];
    const float* b1  = (const float*)d_in[5];
    const float* Ws2 = (const float*)d_in[6];
    const float* Wn2 = (const float*)d_in[7];
    const float* b2  = (const float*)d_in[8];
    float* out = (float*)d_out;

    float *p_deg, *p_agg1, *p_agg2, *p_h1, *p_t2, *p_W1, *p_W2s, *p_W2n;
    cudaGetSymbolAddress((void**)&p_deg,  g_deg);
    cudaGetSymbolAddress((void**)&p_agg1, g_agg1);
    cudaGetSymbolAddress((void**)&p_agg2, g_agg2);
    cudaGetSymbolAddress((void**)&p_h1,   g_h1);
    cudaGetSymbolAddress((void**)&p_t2,   g_t2);
    cudaGetSymbolAddress((void**)&p_W1,   g_W1cat);
    cudaGetSymbolAddress((void**)&p_W2s,  g_W2s);
    cudaGetSymbolAddress((void**)&p_W2n,  g_W2n);

    // 1) zero deg + agg buffers
    zero_f4<<<128, 256>>>((float4*)p_deg, (size_t)N_NODES / 4);
    zero_f4<<<2048, 256>>>((float4*)p_agg1, (size_t)N_NODES * F_IN / 4);
    zero_f4<<<2048, 256>>>((float4*)p_agg2, (size_t)N_NODES * N_OUT / 4);

    // 2) padded/concatenated weights
    prep_weights<<<(W1_ROWS * W1_COLS + 255) / 256, 256>>>(Ws1, Wn1, Ws2, Wn2);

    // 3) degree + inverse
    deg_kernel<<<(N_EDGES + 255) / 256, 256>>>(dst);
    deginv_kernel<<<(N_NODES + 255) / 256, 256>>>();

    // 4) scatter x into agg1
    {
        long long threads = (long long)N_EDGES * 32;
        int blocks = (int)((threads + 255) / 256);
        scatter128<<<blocks, 256>>>(x, src, dst, p_agg1);
    }

    // 5) layer 1 fused GEMM -> h1 (relu)
    {
        dim3 grid(3, (N_NODES + 63) / 64);
        gemm_kernel<1><<<grid, 256>>>(x, p_agg1, p_W1, b1, nullptr, p_h1,
                                      N_NODES, HID, W1_ROWS, 128, W1_COLS, HID_PAD);
    }

    // 6) t2 = h1 @ W_neigh2
    {
        dim3 grid(2, (N_NODES + 63) / 64);
        gemm_kernel<2><<<grid, 256>>>(p_h1, nullptr, p_W2n, nullptr, nullptr, p_t2,
                                      N_NODES, N_OUT, HID_PAD, HID_PAD, N_OUT, N_OUT);
    }

    // 7) scatter t2 into agg2
    {
        long long threads = (long long)N_EDGES * 32;
        int blocks = (int)((threads + 255) / 256);
        scatter128<<<blocks, 256>>>(p_t2, src, dst, p_agg2);
    }

    // 8) out = h1 @ W_self2 + b2 + deginv*agg2
    {
        dim3 grid(2, (N_NODES + 63) / 64);
        gemm_kernel<3><<<grid, 256>>>(p_h1, nullptr, p_W2s, b2, p_agg2, out,
                                      N_NODES, N_OUT, HID_PAD, HID_PAD, N_OUT, N_OUT);
    }
}

// round 4
// speedup vs baseline: 1.2687x; 1.2687x over previous
#include <cuda_runtime.h>
#include <cuda_bf16.h>
#include <cstdint>
#include <cstddef>

#define N_NODES 100000
#define N_EDGES 1600000
#define F_IN    128
#define HID     150
#define K1      256      // layer1 K: 128 self + 128 neigh
#define K2      192      // layer2 K: 150 padded to 192
#define N1      192      // layer1 out cols: 150 padded to 192
#define N_OUT   128

// ---------------- scratch (static device globals) ----------------------------
__device__ __align__(16) float g_deg[N_NODES];
__device__ __align__(16) float g_deginv[N_NODES];
__device__ __align__(16) float g_agg1[(size_t)N_NODES * F_IN];
__device__ __align__(16) float g_agg2[(size_t)N_NODES * N_OUT];
__device__ __align__(16) float g_t2[(size_t)N_NODES * N_OUT];
__device__ __align__(16) float g_h1[(size_t)N_NODES * K2];     // fp32, padded cols = 0
__device__ __align__(16) __nv_bfloat16 g_Wt1hi[N1 * K1];
__device__ __align__(16) __nv_bfloat16 g_Wt1lo[N1 * K1];
__device__ __align__(16) __nv_bfloat16 g_Wt2nhi[N_OUT * K2];
__device__ __align__(16) __nv_bfloat16 g_Wt2nlo[N_OUT * K2];
__device__ __align__(16) __nv_bfloat16 g_Wt2shi[N_OUT * K2];
__device__ __align__(16) __nv_bfloat16 g_Wt2slo[N_OUT * K2];
__device__ __align__(16) float g_b1p[N1];

// ---------------- helpers ------------------------------------------------------
__device__ __forceinline__ void split_bf16(float v, __nv_bfloat16& h, __nv_bfloat16& l) {
    h = __float2bfloat16_rn(v);
    l = __float2bfloat16_rn(v - __bfloat162float(h));
}

// split two fp32 into packed bf16x2 hi / lo words
__device__ __forceinline__ void split2(float v0, float v1, uint32_t& hi, uint32_t& lo) {
    __nv_bfloat16 h0, l0, h1, l1;
    split_bf16(v0, h0, l0);
    split_bf16(v1, h1, l1);
    hi = (uint32_t)__bfloat16_as_ushort(h0) | ((uint32_t)__bfloat16_as_ushort(h1) << 16);
    lo = (uint32_t)__bfloat16_as_ushort(l0) | ((uint32_t)__bfloat16_as_ushort(l1) << 16);
}

__device__ __forceinline__ void mma16816(float* d, const uint32_t* a, const uint32_t* b) {
    asm volatile(
        "mma.sync.aligned.m16n8k16.row.col.f32.bf16.bf16.f32 "
        "{%0,%1,%2,%3}, {%4,%5,%6,%7}, {%8,%9}, {%0,%1,%2,%3};"
        : "+f"(d[0]), "+f"(d[1]), "+f"(d[2]), "+f"(d[3])
        : "r"(a[0]), "r"(a[1]), "r"(a[2]), "r"(a[3]), "r"(b[0]), "r"(b[1]));
}

// ---------------- small utility kernels --------------------------------------
__global__ void zero_f4(float4* p, size_t n4) {
    size_t i = (size_t)blockIdx.x * blockDim.x + threadIdx.x;
    size_t stride = (size_t)gridDim.x * blockDim.x;
    float4 z = make_float4(0.f, 0.f, 0.f, 0.f);
    for (; i < n4; i += stride) p[i] = z;
}

__global__ void prep_weights(const float* __restrict__ Ws1,
                             const float* __restrict__ Wn1,
                             const float* __restrict__ Ws2,
                             const float* __restrict__ Wn2,
                             const float* __restrict__ b1) {
    int i = blockIdx.x * blockDim.x + threadIdx.x;
    if (i < N1 * K1) {
        int n = i / K1, k = i % K1;
        float w = 0.f;
        if (n < HID) w = (k < F_IN) ? Ws1[k * HID + n] : Wn1[(k - F_IN) * HID + n];
        split_bf16(w, g_Wt1hi[i], g_Wt1lo[i]);
    }
    if (i < N_OUT * K2) {
        int n = i / K2, k = i % K2;
        float ws = (k < HID) ? Ws2[k * N_OUT + n] : 0.f;
        float wn = (k < HID) ? Wn2[k * N_OUT + n] : 0.f;
        split_bf16(ws, g_Wt2shi[i], g_Wt2slo[i]);
        split_bf16(wn, g_Wt2nhi[i], g_Wt2nlo[i]);
    }
    if (i < N1) g_b1p[i] = (i < HID) ? b1[i] : 0.f;
}

__global__ void deg_kernel(const int* __restrict__ dst) {
    int e = blockIdx.x * blockDim.x + threadIdx.x;
    if (e < N_EDGES) atomicAdd(&g_deg[dst[e]], 1.0f);
}

__global__ void deginv_kernel() {
    int i = blockIdx.x * blockDim.x + threadIdx.x;
    if (i < N_NODES) {
        float d = g_deg[i];
        g_deginv[i] = (d > 0.f) ? (1.0f / d) : 0.f;
    }
}

// one warp per edge; 32 lanes * float4 = 128 features
__global__ void scatter128(const float* __restrict__ feat,
                           const int* __restrict__ src,
                           const int* __restrict__ dst,
                           float* __restrict__ out) {
    long long gid = (long long)blockIdx.x * blockDim.x + threadIdx.x;
    int e = (int)(gid >> 5);
    int lane = (int)(gid & 31);
    if (e >= N_EDGES) return;
    int s = __ldg(&src[e]);
    int d = __ldg(&dst[e]);
    float4 v = ((const float4*)feat)[(size_t)s * 32 + lane];
    float* p = out + (size_t)d * 128 + lane * 4;
    asm volatile("red.global.add.v4.f32 [%0], {%1, %2, %3, %4};"
                 :: "l"(p), "f"(v.x), "f"(v.y), "f"(v.z), "f"(v.w) : "memory");
}

// ---------------- mma.sync split-bf16 GEMM -------------------------------------
// C[m][n] = sum_k A[m][k]*B[n][k] ; A fp32 (converted to hi/lo bf16 in staging),
// B pre-split bf16 hi/lo in global ([n][k], k contiguous).
// Tiles: BM=128, BN=64, BK=32. 8 warps (4 m x 2 n), each warp 32x32 via 2x4 m16n8k16.
// MODE 1: A = [x | deginv*agg1] (K=256), out h1 = relu(C + b1p), ldc=192
// MODE 2: A = h1 (K=192), out t2 = C, ldc=128
// MODE 3: A = h1 (K=192), out = C + b2 + deginv[row]*agg2[row][col], ldc=128
#define SMW 20   // smem row stride in 32-bit words (40 bf16 = 80B; conflict-free)
template <int MODE, int KCH>
__global__ void __launch_bounds__(256)
mma_gemm(const float* __restrict__ A, const float* __restrict__ A2,
         const __nv_bfloat16* __restrict__ Bhi, const __nv_bfloat16* __restrict__ Blo,
         const float* __restrict__ bias, const float* __restrict__ addin,
         float* __restrict__ C, int M, int lda, int ldc) {
    constexpr int KTOT = KCH * 32;
    __shared__ uint32_t Ash[128 * SMW];
    __shared__ uint32_t Asl[128 * SMW];
    __shared__ uint32_t Bsh[64 * SMW];
    __shared__ uint32_t Bsl[64 * SMW];

    int tid = threadIdx.x, wid = tid >> 5, lid = tid & 31;
    int warp_m = wid & 3, warp_n = wid >> 2;
    int g = lid >> 2, q = lid & 3;
    int row0 = blockIdx.y * 128, n0 = blockIdx.x * 64;

    float acc[2][4][4];
#pragma unroll
    for (int mt = 0; mt < 2; mt++)
#pragma unroll
        for (int nt = 0; nt < 4; nt++)
#pragma unroll
            for (int r = 0; r < 4; r++) acc[mt][nt][r] = 0.f;

    // staging assignments
    int srow = tid >> 1, shalf = tid & 1;      // A: 128 rows x 2 halves (16 floats each)
    int grow = row0 + srow;
    int brow = tid >> 2, bseg = tid & 3;       // B: 64 rows x 4 segs (8 bf16 each)

    float dv1 = 0.f;
    if (MODE == 1 && grow < M) dv1 = g_deginv[grow];

    for (int c = 0; c < KCH; c++) {
        // global loads
        uint4 bh = *(const uint4*)(Bhi + (size_t)(n0 + brow) * KTOT + c * 32 + bseg * 8);
        uint4 bl = *(const uint4*)(Blo + (size_t)(n0 + brow) * KTOT + c * 32 + bseg * 8);
        float4 f[4];
#pragma unroll
        for (int i = 0; i < 4; i++) f[i] = make_float4(0.f, 0.f, 0.f, 0.f);
        if (grow < M) {
            const float* sp;
            if (MODE == 1) {
                sp = (c < 4) ? (A + (size_t)grow * 128 + c * 32)
                             : (A2 + (size_t)grow * 128 + (c - 4) * 32);
            } else {
                sp = A + (size_t)grow * lda + c * 32;
            }
            const float4* p = (const float4*)(sp + shalf * 16);
#pragma unroll
            for (int i = 0; i < 4; i++) f[i] = p[i];
            if (MODE == 1 && c >= 4) {
#pragma unroll
                for (int i = 0; i < 4; i++) {
                    f[i].x *= dv1; f[i].y *= dv1; f[i].z *= dv1; f[i].w *= dv1;
                }
            }
        }

        __syncthreads();   // previous iteration's fragment reads complete

        // store B tile
        *(uint4*)&Bsh[brow * SMW + bseg * 4] = bh;
        *(uint4*)&Bsl[brow * SMW + bseg * 4] = bl;
        // convert + store A tile
        {
            int base = srow * SMW + shalf * 8;
            float fv[16] = {f[0].x, f[0].y, f[0].z, f[0].w, f[1].x, f[1].y, f[1].z, f[1].w,
                            f[2].x, f[2].y, f[2].z, f[2].w, f[3].x, f[3].y, f[3].z, f[3].w};
#pragma unroll
            for (int j = 0; j < 8; j++) {
                uint32_t hi, lo;
                split2(fv[2 * j], fv[2 * j + 1], hi, lo);
                Ash[base + j] = hi;
                Asl[base + j] = lo;
            }
        }
        __syncthreads();

        // compute: 2 k16 steps x 3 passes x (2x4) mma
#pragma unroll
        for (int ks = 0; ks < 2; ks++) {
            uint32_t ah[2][4], al[2][4], bhf[4][2], blf[4][2];
#pragma unroll
            for (int mt = 0; mt < 2; mt++) {
                int ar = warp_m * 32 + mt * 16 + g;
                int base = ar * SMW + ks * 8;
                ah[mt][0] = Ash[base + q];
                ah[mt][1] = Ash[base + 8 * SMW + q];
                ah[mt][2] = Ash[base + q + 4];
                ah[mt][3] = Ash[base + 8 * SMW + q + 4];
                al[mt][0] = Asl[base + q];
                al[mt][1] = Asl[base + 8 * SMW + q];
                al[mt][2] = Asl[base + q + 4];
                al[mt][3] = Asl[base + 8 * SMW + q + 4];
            }
#pragma unroll
            for (int nt = 0; nt < 4; nt++) {
                int bn = warp_n * 32 + nt * 8 + g;
                int base = bn * SMW + ks * 8;
                bhf[nt][0] = Bsh[base + q];
                bhf[nt][1] = Bsh[base + q + 4];
                blf[nt][0] = Bsl[base + q];
                blf[nt][1] = Bsl[base + q + 4];
            }
#pragma unroll
            for (int mt = 0; mt < 2; mt++)
#pragma unroll
                for (int nt = 0; nt < 4; nt++) {
                    mma16816(acc[mt][nt], ah[mt], bhf[nt]);
                    mma16816(acc[mt][nt], ah[mt], blf[nt]);
                    mma16816(acc[mt][nt], al[mt], bhf[nt]);
                }
        }
    }

    // epilogue: thread owns rows (r0, r0+8), cols cb, cb+1 per (mt, nt)
#pragma unroll
    for (int mt = 0; mt < 2; mt++) {
        int r0 = row0 + warp_m * 32 + mt * 16 + g;
        float dva = 0.f, dvb = 0.f;
        if (MODE == 3) {
            if (r0 < M) dva = g_deginv[r0];
            if (r0 + 8 < M) dvb = g_deginv[r0 + 8];
        }
#pragma unroll
        for (int nt = 0; nt < 4; nt++) {
            int cb = n0 + warp_n * 32 + nt * 8 + q * 2;
            float v0 = acc[mt][nt][0], v1 = acc[mt][nt][1];
            float v2 = acc[mt][nt][2], v3 = acc[mt][nt][3];
            if (MODE == 1) {
                float b0 = __ldg(&bias[cb]), b1v = __ldg(&bias[cb + 1]);
                v0 = fmaxf(v0 + b0, 0.f); v1 = fmaxf(v1 + b1v, 0.f);
                v2 = fmaxf(v2 + b0, 0.f); v3 = fmaxf(v3 + b1v, 0.f);
            } else if (MODE == 3) {
                float b0 = __ldg(&bias[cb]), b1v = __ldg(&bias[cb + 1]);
                if (r0 < M) {
                    const float2 a = *(const float2*)(addin + (size_t)r0 * 128 + cb);
                    v0 += b0 + dva * a.x; v1 += b1v + dva * a.y;
                }
                if (r0 + 8 < M) {
                    const float2 a = *(const float2*)(addin + (size_t)(r0 + 8) * 128 + cb);
                    v2 += b0 + dvb * a.x; v3 += b1v + dvb * a.y;
                }
            }
            if (r0 < M) *(float2*)(C + (size_t)r0 * ldc + cb) = make_float2(v0, v1);
            if (r0 + 8 < M) *(float2*)(C + (size_t)(r0 + 8) * ldc + cb) = make_float2(v2, v3);
        }
    }
}

// ---------------- launch --------------------------------------------------------
extern "C" void kernel_launch(void* const* d_in, const int* in_sizes, int n_in,
                              void* d_out, int out_size) {
    const float* x   = (const float*)d_in[0];
    const int*   src = (const int*)d_in[1];
    const int*   dst = (const int*)d_in[2];
    const float* Ws1 = (const float*)d_in[3];
    const float* Wn1 = (const float*)d_in[4];
    const float* b1  = (const float*)d_in[5];
    const float* Ws2 = (const float*)d_in[6];
    const float* Wn2 = (const float*)d_in[7];
    const float* b2  = (const float*)d_in[8];
    float* out = (float*)d_out;

    float *p_deg, *p_agg1, *p_agg2, *p_t2, *p_h1, *p_b1p;
    __nv_bfloat16 *p_W1hi, *p_W1lo, *p_W2nhi, *p_W2nlo, *p_W2shi, *p_W2slo;
    cudaGetSymbolAddress((void**)&p_deg,   g_deg);
    cudaGetSymbolAddress((void**)&p_agg1,  g_agg1);
    cudaGetSymbolAddress((void**)&p_agg2,  g_agg2);
    cudaGetSymbolAddress((void**)&p_t2,    g_t2);
    cudaGetSymbolAddress((void**)&p_h1,    g_h1);
    cudaGetSymbolAddress((void**)&p_b1p,   g_b1p);
    cudaGetSymbolAddress((void**)&p_W1hi,  g_Wt1hi);
    cudaGetSymbolAddress((void**)&p_W1lo,  g_Wt1lo);
    cudaGetSymbolAddress((void**)&p_W2nhi, g_Wt2nhi);
    cudaGetSymbolAddress((void**)&p_W2nlo, g_Wt2nlo);
    cudaGetSymbolAddress((void**)&p_W2shi, g_Wt2shi);
    cudaGetSymbolAddress((void**)&p_W2slo, g_Wt2slo);

    const int MROWS = (N_NODES + 127) / 128;  // 782

    // 1) zero deg + agg buffers
    zero_f4<<<128, 256>>>((float4*)p_deg, (size_t)N_NODES / 4);
    zero_f4<<<2048, 256>>>((float4*)p_agg1, (size_t)N_NODES * F_IN / 4);
    zero_f4<<<2048, 256>>>((float4*)p_agg2, (size_t)N_NODES * N_OUT / 4);

    // 2) weights (transpose + pad + bf16 split)
    prep_weights<<<(N1 * K1 + 255) / 256, 256>>>(Ws1, Wn1, Ws2, Wn2, b1);

    // 3) degree + inverse
    deg_kernel<<<(N_EDGES + 255) / 256, 256>>>(dst);
    deginv_kernel<<<(N_NODES + 255) / 256, 256>>>();

    // 4) scatter x into agg1
    {
        long long threads = (long long)N_EDGES * 32;
        scatter128<<<(int)((threads + 255) / 256), 256>>>(x, src, dst, p_agg1);
    }

    // 5) layer-1 GEMM -> h1 (fp32, bias+relu), N tiles {0,64,128}, K=256
    mma_gemm<1, 8><<<dim3(3, MROWS), 256>>>(
        x, p_agg1, p_W1hi, p_W1lo, p_b1p, nullptr, p_h1, N_NODES, 128, K2);

    // 6) t2 = h1 @ W_neigh2   (K=192)
    mma_gemm<2, 6><<<dim3(2, MROWS), 256>>>(
        p_h1, nullptr, p_W2nhi, p_W2nlo, nullptr, nullptr, p_t2, N_NODES, K2, N_OUT);

    // 7) scatter t2 into agg2
    {
        long long threads = (long long)N_EDGES * 32;
        scatter128<<<(int)((threads + 255) / 256), 256>>>(p_t2, src, dst, p_agg2);
    }

    // 8) out = h1 @ W_self2 + b2 + deginv*agg2   (K=192)
    mma_gemm<3, 6><<<dim3(2, MROWS), 256>>>(
        p_h1, nullptr, p_W2shi, p_W2slo, b2, p_agg2, out, N_NODES, K2, N_OUT);
}

// round 5
// speedup vs baseline: 2.1904x; 1.7265x over previous
#include <cuda_runtime.h>
#include <cuda_bf16.h>
#include <cstdint>
#include <cstddef>

#define N_NODES 100000
#define N_EDGES 1600000
#define F_IN    128
#define HID     150
#define K1      256      // layer1 K: 128 self + 128 neigh
#define K2      192      // layer2 K: 150 padded to 192
#define N1      192      // layer1 out cols: 150 padded to 192
#define N_OUT   128
#define NB      391      // ceil(N_NODES/256)
#define SMW     20       // smem row stride in 32-bit words (16 used + 4 pad)

// ---------------- scratch (static device globals) ----------------------------
__device__ __align__(16) int g_cnt[N_NODES];
__device__ __align__(16) int g_excl[N_NODES];
__device__ __align__(16) int g_bsum[512];
__device__ __align__(16) int g_bsumx[512];
__device__ __align__(16) int g_rowptr[N_NODES + 1];
__device__ __align__(16) int g_cur[N_NODES];
__device__ __align__(16) int g_col[N_EDGES];
__device__ __align__(16) float g_agg1n[(size_t)N_NODES * F_IN];   // deginv-scaled
__device__ __align__(16) float g_h1[(size_t)N_NODES * K2];
__device__ __align__(16) float g_t2[(size_t)N_NODES * N_OUT];
__device__ __align__(16) __nv_bfloat16 g_W1hi[N1 * K1];
__device__ __align__(16) __nv_bfloat16 g_W1lo[N1 * K1];
__device__ __align__(16) __nv_bfloat16 g_Bchi[256 * K2];   // [Wn2 | Ws2] concat, row=out col
__device__ __align__(16) __nv_bfloat16 g_Bclo[256 * K2];
__device__ __align__(16) float g_b1p[N1];

// ---------------- helpers ------------------------------------------------------
__device__ __forceinline__ void split_bf16(float v, __nv_bfloat16& h, __nv_bfloat16& l) {
    h = __float2bfloat16_rn(v);
    l = __float2bfloat16_rn(v - __bfloat162float(h));
}
__device__ __forceinline__ void split2(float v0, float v1, uint32_t& hi, uint32_t& lo) {
    __nv_bfloat16 h0, l0, h1, l1;
    split_bf16(v0, h0, l0);
    split_bf16(v1, h1, l1);
    hi = (uint32_t)__bfloat16_as_ushort(h0) | ((uint32_t)__bfloat16_as_ushort(h1) << 16);
    lo = (uint32_t)__bfloat16_as_ushort(l0) | ((uint32_t)__bfloat16_as_ushort(l1) << 16);
}
__device__ __forceinline__ void mma16816(float* d, const uint32_t* a, const uint32_t* b) {
    asm volatile(
        "mma.sync.aligned.m16n8k16.row.col.f32.bf16.bf16.f32 "
        "{%0,%1,%2,%3}, {%4,%5,%6,%7}, {%8,%9}, {%0,%1,%2,%3};"
        : "+f"(d[0]), "+f"(d[1]), "+f"(d[2]), "+f"(d[3])
        : "r"(a[0]), "r"(a[1]), "r"(a[2]), "r"(a[3]), "r"(b[0]), "r"(b[1]));
}

// ---------------- CSR build ----------------------------------------------------
__global__ void zero_cnt() {
    int i = blockIdx.x * blockDim.x + threadIdx.x;
    if (i < N_NODES / 4) ((int4*)g_cnt)[i] = make_int4(0, 0, 0, 0);
}
__global__ void hist_kernel(const int* __restrict__ dst) {
    int e = blockIdx.x * blockDim.x + threadIdx.x;
    if (e < N_EDGES) atomicAdd(&g_cnt[dst[e]], 1);
}
__global__ void scan1_kernel() {
    __shared__ int sh[256];
    int tid = threadIdx.x;
    int i = blockIdx.x * 256 + tid;
    int v = (i < N_NODES) ? g_cnt[i] : 0;
    sh[tid] = v;
    __syncthreads();
#pragma unroll
    for (int off = 1; off < 256; off <<= 1) {
        int t = (tid >= off) ? sh[tid - off] : 0;
        __syncthreads();
        sh[tid] += t;
        __syncthreads();
    }
    if (i < N_NODES) g_excl[i] = sh[tid] - v;
    if (tid == 255) g_bsum[blockIdx.x] = sh[255];
}
__global__ void scan2_kernel() {
    __shared__ int sh[512];
    int tid = threadIdx.x;
    int v = (tid < NB) ? g_bsum[tid] : 0;
    sh[tid] = v;
    __syncthreads();
#pragma unroll
    for (int off = 1; off < 512; off <<= 1) {
        int t = (tid >= off) ? sh[tid - off] : 0;
        __syncthreads();
        sh[tid] += t;
        __syncthreads();
    }
    g_bsumx[tid] = sh[tid] - v;
}
__global__ void scan3_kernel() {
    int i = blockIdx.x * 256 + threadIdx.x;
    if (i < N_NODES) {
        int r = g_excl[i] + g_bsumx[i >> 8];
        g_rowptr[i] = r;
        g_cur[i] = r;
    }
    if (i == 0) g_rowptr[N_NODES] = N_EDGES;
}
__global__ void fill_kernel(const int* __restrict__ src, const int* __restrict__ dst) {
    int e = blockIdx.x * blockDim.x + threadIdx.x;
    if (e < N_EDGES) {
        int pos = atomicAdd(&g_cur[dst[e]], 1);
        g_col[pos] = src[e];
    }
}

// ---------------- gather (warp per node, 128 feats) ---------------------------
// FUSE=0: outp[v] = deginv * sum_{e} feat[col[e]]
// FUSE=1: outp[v] += deginv * sum_{e} feat[col[e]]
template <int FUSE>
__global__ void __launch_bounds__(256) gather128(const float* __restrict__ feat,
                                                 float* __restrict__ outp) {
    int gid = blockIdx.x * 256 + threadIdx.x;
    int v = gid >> 5, lane = gid & 31;
    if (v >= N_NODES) return;
    int beg = g_rowptr[v], end = g_rowptr[v + 1];
    float4 acc = make_float4(0.f, 0.f, 0.f, 0.f);
    const float4* f4 = (const float4*)feat;
    int e = beg;
    for (; e + 4 <= end; e += 4) {
        int s0 = __ldg(&g_col[e]), s1 = __ldg(&g_col[e + 1]);
        int s2 = __ldg(&g_col[e + 2]), s3 = __ldg(&g_col[e + 3]);
        float4 a = __ldg(f4 + (size_t)s0 * 32 + lane);
        float4 b = __ldg(f4 + (size_t)s1 * 32 + lane);
        float4 c = __ldg(f4 + (size_t)s2 * 32 + lane);
        float4 d = __ldg(f4 + (size_t)s3 * 32 + lane);
        acc.x += (a.x + b.x) + (c.x + d.x);
        acc.y += (a.y + b.y) + (c.y + d.y);
        acc.z += (a.z + b.z) + (c.z + d.z);
        acc.w += (a.w + b.w) + (c.w + d.w);
    }
    for (; e < end; e++) {
        int s = __ldg(&g_col[e]);
        float4 a = __ldg(f4 + (size_t)s * 32 + lane);
        acc.x += a.x; acc.y += a.y; acc.z += a.z; acc.w += a.w;
    }
    float dv = (end > beg) ? (1.f / (float)(end - beg)) : 0.f;
    size_t o = (size_t)v * 32 + lane;
    if (FUSE) {
        float4 cur = ((float4*)outp)[o];
        cur.x += dv * acc.x; cur.y += dv * acc.y;
        cur.z += dv * acc.z; cur.w += dv * acc.w;
        ((float4*)outp)[o] = cur;
    } else {
        acc.x *= dv; acc.y *= dv; acc.z *= dv; acc.w *= dv;
        ((float4*)outp)[o] = acc;
    }
}

// ---------------- weight prep --------------------------------------------------
__global__ void prep_weights(const float* __restrict__ Ws1,
                             const float* __restrict__ Wn1,
                             const float* __restrict__ Ws2,
                             const float* __restrict__ Wn2,
                             const float* __restrict__ b1) {
    int i = blockIdx.x * blockDim.x + threadIdx.x;
    if (i < N1 * K1) {   // W1: row n (out col), k contiguous
        int n = i / K1, k = i % K1;
        float w = 0.f;
        if (n < HID) w = (k < F_IN) ? Ws1[k * HID + n] : Wn1[(k - F_IN) * HID + n];
        split_bf16(w, g_W1hi[i], g_W1lo[i]);
    }
    if (i < 256 * K2) {  // Bcat: rows 0..127 = Wn2 cols, 128..255 = Ws2 cols
        int n = i / K2, k = i % K2;
        float w = 0.f;
        if (k < HID) w = (n < 128) ? Wn2[k * N_OUT + n] : Ws2[k * N_OUT + (n - 128)];
        split_bf16(w, g_Bchi[i], g_Bclo[i]);
    }
    if (i < N1) g_b1p[i] = (i < HID) ? b1[i] : 0.f;
}

// ---------------- mma.sync split-bf16 GEMM, double-buffered --------------------
// BM=64, BN full width. 8 warps (2 m x 4 n). C = sum_k A[m][k]*B[n][k].
// MODE 1: A = [x | agg1n] (K=256), h1 = relu(C + b1p), ldc=192
// MODE 2: A = h1 (K=192), B = [Wn2|Ws2] (N=256):
//         cols<128 -> t2 = C ; cols>=128 -> out = C + b2
template <int MODE>
__global__ void __launch_bounds__(256, 1)
mma_gemm(const float* __restrict__ A, const float* __restrict__ A2,
         const __nv_bfloat16* __restrict__ Bhi, const __nv_bfloat16* __restrict__ Blo,
         const float* __restrict__ bias, float* __restrict__ C, float* __restrict__ C2) {
    constexpr int BN   = (MODE == 1) ? 192 : 256;
    constexpr int KCH  = (MODE == 1) ? 8 : 6;
    constexpr int KTOT = KCH * 32;
    constexpr int NT   = BN / 32;        // per-warp n-tiles (warp covers BN/4 cols)
    constexpr int BCNT = BN * 4 / 256;   // uint4 B loads per thread
    constexpr int AW   = 64 * SMW;
    constexpr int BW   = BN * SMW;
    constexpr int BUF  = 2 * AW + 2 * BW;

    extern __shared__ uint32_t sm[];
    int tid = threadIdx.x, wid = tid >> 5, lid = tid & 31;
    int warp_m = wid & 1, warp_n = wid >> 1;
    int g = lid >> 2, q = lid & 3;
    int row0 = blockIdx.x * 64;

    float acc[2][NT][4];
#pragma unroll
    for (int mt = 0; mt < 2; mt++)
#pragma unroll
        for (int nt = 0; nt < NT; nt++)
#pragma unroll
            for (int r = 0; r < 4; r++) acc[mt][nt][r] = 0.f;

    int srow = tid >> 2, sseg = tid & 3;
    int grow = row0 + srow;

    float fa[8];
    uint4 bhv[BCNT], blv[BCNT];

    auto ldg_tile = [&](int c) {
#pragma unroll
        for (int j = 0; j < 8; j++) fa[j] = 0.f;
        if (grow < N_NODES) {
            const float* sp;
            if (MODE == 1)
                sp = (c < 4) ? (A + (size_t)grow * 128 + c * 32)
                             : (A2 + (size_t)grow * 128 + (c - 4) * 32);
            else
                sp = A + (size_t)grow * K2 + c * 32;
            float4 p0 = *(const float4*)(sp + sseg * 8);
            float4 p1 = *(const float4*)(sp + sseg * 8 + 4);
            fa[0] = p0.x; fa[1] = p0.y; fa[2] = p0.z; fa[3] = p0.w;
            fa[4] = p1.x; fa[5] = p1.y; fa[6] = p1.z; fa[7] = p1.w;
        }
#pragma unroll
        for (int j = 0; j < BCNT; j++) {
            int u = tid + j * 256;
            int row = u >> 2, seg = u & 3;
            bhv[j] = *(const uint4*)(Bhi + (size_t)row * KTOT + c * 32 + seg * 8);
            blv[j] = *(const uint4*)(Blo + (size_t)row * KTOT + c * 32 + seg * 8);
        }
    };
    auto sts_tile = [&](int b) {
        uint32_t* Ash = sm + b * BUF;
        uint32_t* Asl = Ash + AW;
        uint32_t* Bsh = Asl + AW;
        uint32_t* Bsl = Bsh + BW;
        int base = srow * SMW + sseg * 4;
#pragma unroll
        for (int j = 0; j < 4; j++) {
            uint32_t hi, lo;
            split2(fa[2 * j], fa[2 * j + 1], hi, lo);
            Ash[base + j] = hi;
            Asl[base + j] = lo;
        }
#pragma unroll
        for (int j = 0; j < BCNT; j++) {
            int u = tid + j * 256;
            int row = u >> 2, seg = u & 3;
            *(uint4*)&Bsh[row * SMW + seg * 4] = bhv[j];
            *(uint4*)&Bsl[row * SMW + seg * 4] = blv[j];
        }
    };

    ldg_tile(0);
    sts_tile(0);
    __syncthreads();

    for (int c = 0; c < KCH; c++) {
        if (c + 1 < KCH) ldg_tile(c + 1);

        uint32_t* Ash = sm + (c & 1) * BUF;
        uint32_t* Asl = Ash + AW;
        uint32_t* Bsh = Asl + AW;
        uint32_t* Bsl = Bsh + BW;
#pragma unroll
        for (int ks = 0; ks < 2; ks++) {
            uint32_t ah[2][4], al[2][4];
#pragma unroll
            for (int mt = 0; mt < 2; mt++) {
                int base = (warp_m * 32 + mt * 16 + g) * SMW + ks * 8;
                ah[mt][0] = Ash[base + q];
                ah[mt][1] = Ash[base + 8 * SMW + q];
                ah[mt][2] = Ash[base + q + 4];
                ah[mt][3] = Ash[base + 8 * SMW + q + 4];
                al[mt][0] = Asl[base + q];
                al[mt][1] = Asl[base + 8 * SMW + q];
                al[mt][2] = Asl[base + q + 4];
                al[mt][3] = Asl[base + 8 * SMW + q + 4];
            }
#pragma unroll
            for (int nt = 0; nt < NT; nt++) {
                int base = (warp_n * (BN / 4) + nt * 8 + g) * SMW + ks * 8;
                uint32_t bh2[2], bl2[2];
                bh2[0] = Bsh[base + q]; bh2[1] = Bsh[base + q + 4];
                bl2[0] = Bsl[base + q]; bl2[1] = Bsl[base + q + 4];
#pragma unroll
                for (int mt = 0; mt < 2; mt++) {
                    mma16816(acc[mt][nt], ah[mt], bh2);
                    mma16816(acc[mt][nt], ah[mt], bl2);
                    mma16816(acc[mt][nt], al[mt], bh2);
                }
            }
        }
        if (c + 1 < KCH) {
            sts_tile((c + 1) & 1);
            __syncthreads();
        }
    }

    // epilogue
#pragma unroll
    for (int mt = 0; mt < 2; mt++) {
        int r0 = row0 + warp_m * 32 + mt * 16 + g;
#pragma unroll
        for (int nt = 0; nt < NT; nt++) {
            int cb = warp_n * (BN / 4) + nt * 8 + q * 2;
            float v0 = acc[mt][nt][0], v1 = acc[mt][nt][1];
            float v2 = acc[mt][nt][2], v3 = acc[mt][nt][3];
            if (MODE == 1) {
                float b0 = __ldg(&bias[cb]), b1v = __ldg(&bias[cb + 1]);
                v0 = fmaxf(v0 + b0, 0.f); v1 = fmaxf(v1 + b1v, 0.f);
                v2 = fmaxf(v2 + b0, 0.f); v3 = fmaxf(v3 + b1v, 0.f);
                if (r0 < N_NODES)     *(float2*)(C + (size_t)r0 * K2 + cb) = make_float2(v0, v1);
                if (r0 + 8 < N_NODES) *(float2*)(C + (size_t)(r0 + 8) * K2 + cb) = make_float2(v2, v3);
            } else {
                if (cb < 128) {
                    if (r0 < N_NODES)     *(float2*)(C + (size_t)r0 * 128 + cb) = make_float2(v0, v1);
                    if (r0 + 8 < N_NODES) *(float2*)(C + (size_t)(r0 + 8) * 128 + cb) = make_float2(v2, v3);
                } else {
                    int oc = cb - 128;
                    float b0 = __ldg(&bias[oc]), b1v = __ldg(&bias[oc + 1]);
                    v0 += b0; v1 += b1v; v2 += b0; v3 += b1v;
                    if (r0 < N_NODES)     *(float2*)(C2 + (size_t)r0 * 128 + oc) = make_float2(v0, v1);
                    if (r0 + 8 < N_NODES) *(float2*)(C2 + (size_t)(r0 + 8) * 128 + oc) = make_float2(v2, v3);
                }
            }
        }
    }
}

// ---------------- launch --------------------------------------------------------
extern "C" void kernel_launch(void* const* d_in, const int* in_sizes, int n_in,
                              void* d_out, int out_size) {
    const float* x   = (const float*)d_in[0];
    const int*   src = (const int*)d_in[1];
    const int*   dst = (const int*)d_in[2];
    const float* Ws1 = (const float*)d_in[3];
    const float* Wn1 = (const float*)d_in[4];
    const float* b1  = (const float*)d_in[5];
    const float* Ws2 = (const float*)d_in[6];
    const float* Wn2 = (const float*)d_in[7];
    const float* b2  = (const float*)d_in[8];
    float* out = (float*)d_out;

    float *p_agg1n, *p_h1, *p_t2, *p_b1p;
    __nv_bfloat16 *p_W1hi, *p_W1lo, *p_Bchi, *p_Bclo;
    cudaGetSymbolAddress((void**)&p_agg1n, g_agg1n);
    cudaGetSymbolAddress((void**)&p_h1,    g_h1);
    cudaGetSymbolAddress((void**)&p_t2,    g_t2);
    cudaGetSymbolAddress((void**)&p_b1p,   g_b1p);
    cudaGetSymbolAddress((void**)&p_W1hi,  g_W1hi);
    cudaGetSymbolAddress((void**)&p_W1lo,  g_W1lo);
    cudaGetSymbolAddress((void**)&p_Bchi,  g_Bchi);
    cudaGetSymbolAddress((void**)&p_Bclo,  g_Bclo);

    constexpr int SMEM1 = 2 * (2 * 64 * SMW + 2 * 192 * SMW) * 4;  // 81920
    constexpr int SMEM2 = 2 * (2 * 64 * SMW + 2 * 256 * SMW) * 4;  // 102400
    cudaFuncSetAttribute(mma_gemm<1>, cudaFuncAttributeMaxDynamicSharedMemorySize, SMEM1);
    cudaFuncSetAttribute(mma_gemm<2>, cudaFuncAttributeMaxDynamicSharedMemorySize, SMEM2);

    const int MB = (N_NODES + 63) / 64;   // 1563

    // CSR build
    zero_cnt<<<98, 256>>>();
    prep_weights<<<192, 256>>>(Ws1, Wn1, Ws2, Wn2, b1);
    hist_kernel<<<N_EDGES / 256, 256>>>(dst);
    scan1_kernel<<<NB, 256>>>();
    scan2_kernel<<<1, 512>>>();
    scan3_kernel<<<NB, 256>>>();
    fill_kernel<<<N_EDGES / 256, 256>>>(src, dst);

    // layer 1
    gather128<0><<<12500, 256>>>(x, p_agg1n);
    mma_gemm<1><<<MB, 256, SMEM1>>>(x, p_agg1n, p_W1hi, p_W1lo, p_b1p, p_h1, nullptr);

    // layer 2 (fused): t2 = h1@Wn2 ; out = h1@Ws2 + b2
    mma_gemm<2><<<MB, 256, SMEM2>>>(p_h1, nullptr, p_Bchi, p_Bclo, b2, p_t2, out);

    // out += deginv * gather(t2)
    gather128<1><<<12500, 256>>>(p_t2, out);
}

// round 6
// speedup vs baseline: 2.2694x; 1.0361x over previous
#include <cuda_runtime.h>
#include <cuda_bf16.h>
#include <cstdint>
#include <cstddef>

#define N_NODES 100000
#define N_EDGES 1600000
#define F_IN    128
#define HID     150
#define K1      256      // layer1 K: 128 self + 128 neigh
#define K2      160      // layer2 K: 150 padded to 160
#define N1      160      // layer1 out cols: 150 padded to 160
#define N_OUT   128
#define NB      391      // ceil(N_NODES/256)
#define SMW     20       // smem row stride in 32-bit words (16 used + 4 pad)

// ---------------- scratch (static device globals) ----------------------------
__device__ __align__(16) int g_cnt[N_NODES];
__device__ __align__(16) int g_excl[N_NODES];
__device__ __align__(16) int g_bsum[512];
__device__ __align__(16) int g_bsumx[512];
__device__ __align__(16) int g_rowptr[N_NODES + 1];
__device__ __align__(16) int g_cur[N_NODES];
__device__ __align__(16) int g_col[N_EDGES];
__device__ __align__(16) int g_wq[2];
__device__ __align__(16) float g_agg1n[(size_t)N_NODES * F_IN];   // deginv-scaled
__device__ __align__(16) float g_h1[(size_t)N_NODES * K2];
__device__ __align__(16) float g_t2[(size_t)N_NODES * N_OUT];
__device__ __align__(16) __nv_bfloat16 g_W1hi[N1 * K1];
__device__ __align__(16) __nv_bfloat16 g_W1lo[N1 * K1];
__device__ __align__(16) __nv_bfloat16 g_Bchi[256 * K2];   // [Wn2 | Ws2] concat, row=out col
__device__ __align__(16) __nv_bfloat16 g_Bclo[256 * K2];
__device__ __align__(16) float g_b1p[N1];

// ---------------- helpers ------------------------------------------------------
__device__ __forceinline__ void split_bf16(float v, __nv_bfloat16& h, __nv_bfloat16& l) {
    h = __float2bfloat16_rn(v);
    l = __float2bfloat16_rn(v - __bfloat162float(h));
}
__device__ __forceinline__ void split2(float v0, float v1, uint32_t& hi, uint32_t& lo) {
    __nv_bfloat16 h0, l0, h1, l1;
    split_bf16(v0, h0, l0);
    split_bf16(v1, h1, l1);
    hi = (uint32_t)__bfloat16_as_ushort(h0) | ((uint32_t)__bfloat16_as_ushort(h1) << 16);
    lo = (uint32_t)__bfloat16_as_ushort(l0) | ((uint32_t)__bfloat16_as_ushort(l1) << 16);
}
__device__ __forceinline__ void mma16816(float* d, const uint32_t* a, const uint32_t* b) {
    asm volatile(
        "mma.sync.aligned.m16n8k16.row.col.f32.bf16.bf16.f32 "
        "{%0,%1,%2,%3}, {%4,%5,%6,%7}, {%8,%9}, {%0,%1,%2,%3};"
        : "+f"(d[0]), "+f"(d[1]), "+f"(d[2]), "+f"(d[3])
        : "r"(a[0]), "r"(a[1]), "r"(a[2]), "r"(a[3]), "r"(b[0]), "r"(b[1]));
}

// ---------------- CSR build ----------------------------------------------------
__global__ void zero_cnt() {
    int i = blockIdx.x * blockDim.x + threadIdx.x;
    if (i < N_NODES / 4) ((int4*)g_cnt)[i] = make_int4(0, 0, 0, 0);
    if (i < 2) g_wq[i] = 0;
}
__global__ void hist_kernel(const int* __restrict__ dst) {
    int e = blockIdx.x * blockDim.x + threadIdx.x;
    if (e < N_EDGES) atomicAdd(&g_cnt[dst[e]], 1);
}
__global__ void scan1_kernel() {
    __shared__ int sh[256];
    int tid = threadIdx.x;
    int i = blockIdx.x * 256 + tid;
    int v = (i < N_NODES) ? g_cnt[i] : 0;
    sh[tid] = v;
    __syncthreads();
#pragma unroll
    for (int off = 1; off < 256; off <<= 1) {
        int t = (tid >= off) ? sh[tid - off] : 0;
        __syncthreads();
        sh[tid] += t;
        __syncthreads();
    }
    if (i < N_NODES) g_excl[i] = sh[tid] - v;
    if (tid == 255) g_bsum[blockIdx.x] = sh[255];
}
__global__ void scan2_kernel() {
    __shared__ int sh[512];
    int tid = threadIdx.x;
    int v = (tid < NB) ? g_bsum[tid] : 0;
    sh[tid] = v;
    __syncthreads();
#pragma unroll
    for (int off = 1; off < 512; off <<= 1) {
        int t = (tid >= off) ? sh[tid - off] : 0;
        __syncthreads();
        sh[tid] += t;
        __syncthreads();
    }
    g_bsumx[tid] = sh[tid] - v;
}
__global__ void scan3_kernel() {
    int i = blockIdx.x * 256 + threadIdx.x;
    if (i < N_NODES) {
        int r = g_excl[i] + g_bsumx[i >> 8];
        g_rowptr[i] = r;
        g_cur[i] = r;
    }
    if (i == 0) g_rowptr[N_NODES] = N_EDGES;
}
__global__ void fill_kernel(const int* __restrict__ src, const int* __restrict__ dst) {
    int e = blockIdx.x * blockDim.x + threadIdx.x;
    if (e < N_EDGES) {
        int pos = atomicAdd(&g_cur[dst[e]], 1);
        g_col[pos] = src[e];
    }
}

// ---------------- gather: persistent warps + work stealing --------------------
// FUSE=0: outp[v] = deginv * sum_{e} feat[col[e]]
// FUSE=1: outp[v] += deginv * sum_{e} feat[col[e]]
template <int FUSE, int QID>
__global__ void __launch_bounds__(256) gather128(const float* __restrict__ feat,
                                                 float* __restrict__ outp) {
    int lane = threadIdx.x & 31;
    const float4* f4 = (const float4*)feat;
    while (true) {
        int base = 0;
        if (lane == 0) base = atomicAdd(&g_wq[QID], 4);
        base = __shfl_sync(0xffffffffu, base, 0);
        if (base >= N_NODES) break;
        int vend = (base + 4 < N_NODES) ? base + 4 : N_NODES;
        for (int v = base; v < vend; v++) {
            int beg = __ldg(&g_rowptr[v]), end = __ldg(&g_rowptr[v + 1]);
            float4 acc = make_float4(0.f, 0.f, 0.f, 0.f);
            int e = beg;
            for (; e + 4 <= end; e += 4) {
                int s0 = __ldg(&g_col[e]), s1 = __ldg(&g_col[e + 1]);
                int s2 = __ldg(&g_col[e + 2]), s3 = __ldg(&g_col[e + 3]);
                float4 a = __ldg(f4 + (size_t)s0 * 32 + lane);
                float4 b = __ldg(f4 + (size_t)s1 * 32 + lane);
                float4 c = __ldg(f4 + (size_t)s2 * 32 + lane);
                float4 d = __ldg(f4 + (size_t)s3 * 32 + lane);
                acc.x += (a.x + b.x) + (c.x + d.x);
                acc.y += (a.y + b.y) + (c.y + d.y);
                acc.z += (a.z + b.z) + (c.z + d.z);
                acc.w += (a.w + b.w) + (c.w + d.w);
            }
            for (; e < end; e++) {
                int s = __ldg(&g_col[e]);
                float4 a = __ldg(f4 + (size_t)s * 32 + lane);
                acc.x += a.x; acc.y += a.y; acc.z += a.z; acc.w += a.w;
            }
            float dv = (end > beg) ? (1.f / (float)(end - beg)) : 0.f;
            size_t o = (size_t)v * 32 + lane;
            if (FUSE) {
                float4 cur = ((float4*)outp)[o];
                cur.x += dv * acc.x; cur.y += dv * acc.y;
                cur.z += dv * acc.z; cur.w += dv * acc.w;
                ((float4*)outp)[o] = cur;
            } else {
                acc.x *= dv; acc.y *= dv; acc.z *= dv; acc.w *= dv;
                ((float4*)outp)[o] = acc;
            }
        }
    }
}

// ---------------- weight prep --------------------------------------------------
__global__ void prep_weights(const float* __restrict__ Ws1,
                             const float* __restrict__ Wn1,
                             const float* __restrict__ Ws2,
                             const float* __restrict__ Wn2,
                             const float* __restrict__ b1) {
    int i = blockIdx.x * blockDim.x + threadIdx.x;
    if (i < N1 * K1) {   // W1: row n (out col), k contiguous
        int n = i / K1, k = i % K1;
        float w = 0.f;
        if (n < HID) w = (k < F_IN) ? Ws1[k * HID + n] : Wn1[(k - F_IN) * HID + n];
        split_bf16(w, g_W1hi[i], g_W1lo[i]);
    }
    if (i < 256 * K2) {  // Bcat: rows 0..127 = Wn2 cols, 128..255 = Ws2 cols
        int n = i / K2, k = i % K2;
        float w = 0.f;
        if (k < HID) w = (n < 128) ? Wn2[k * N_OUT + n] : Ws2[k * N_OUT + (n - 128)];
        split_bf16(w, g_Bchi[i], g_Bclo[i]);
    }
    if (i < N1) g_b1p[i] = (i < HID) ? b1[i] : 0.f;
}

// ---------------- mma.sync split-bf16 GEMM, double-buffered --------------------
// BM=64, BN full width. 8 warps (2 m x 4 n). C = sum_k A[m][k]*B[n][k].
// MODE 1: A = [x | agg1n] (K=256), h1 = relu(C + b1p), BN=160, ldc=160
// MODE 2: A = h1 (K=160), B = [Wn2|Ws2] (N=256):
//         cols<128 -> t2 = C ; cols>=128 -> out = C + b2
template <int MODE>
__global__ void __launch_bounds__(256, 1)
mma_gemm(const float* __restrict__ A, const float* __restrict__ A2,
         const __nv_bfloat16* __restrict__ Bhi, const __nv_bfloat16* __restrict__ Blo,
         const float* __restrict__ bias, float* __restrict__ C, float* __restrict__ C2) {
    constexpr int BN   = (MODE == 1) ? 160 : 256;
    constexpr int KCH  = (MODE == 1) ? 8 : 5;
    constexpr int KTOT = KCH * 32;
    constexpr int NT   = BN / 32;                 // per-warp n-tiles
    constexpr int BCNT = (BN * 4 + 255) / 256;    // guarded uint4 B loads per thread
    constexpr int AW   = 64 * SMW;
    constexpr int BW   = BN * SMW;
    constexpr int BUF  = 2 * AW + 2 * BW;

    extern __shared__ uint32_t sm[];
    int tid = threadIdx.x, wid = tid >> 5, lid = tid & 31;
    int warp_m = wid & 1, warp_n = wid >> 1;
    int g = lid >> 2, q = lid & 3;
    int row0 = blockIdx.x * 64;

    float acc[2][NT][4];
#pragma unroll
    for (int mt = 0; mt < 2; mt++)
#pragma unroll
        for (int nt = 0; nt < NT; nt++)
#pragma unroll
            for (int r = 0; r < 4; r++) acc[mt][nt][r] = 0.f;

    int srow = tid >> 2, sseg = tid & 3;
    int grow = row0 + srow;

    float fa[8];
    uint4 bhv[BCNT], blv[BCNT];

    auto ldg_tile = [&](int c) {
#pragma unroll
        for (int j = 0; j < 8; j++) fa[j] = 0.f;
        if (grow < N_NODES) {
            const float* sp;
            if (MODE == 1)
                sp = (c < 4) ? (A + (size_t)grow * 128 + c * 32)
                             : (A2 + (size_t)grow * 128 + (c - 4) * 32);
            else
                sp = A + (size_t)grow * K2 + c * 32;
            float4 p0 = *(const float4*)(sp + sseg * 8);
            float4 p1 = *(const float4*)(sp + sseg * 8 + 4);
            fa[0] = p0.x; fa[1] = p0.y; fa[2] = p0.z; fa[3] = p0.w;
            fa[4] = p1.x; fa[5] = p1.y; fa[6] = p1.z; fa[7] = p1.w;
        }
#pragma unroll
        for (int j = 0; j < BCNT; j++) {
            int u = tid + j * 256;
            if (u < BN * 4) {
                int row = u >> 2, seg = u & 3;
                bhv[j] = *(const uint4*)(Bhi + (size_t)row * KTOT + c * 32 + seg * 8);
                blv[j] = *(const uint4*)(Blo + (size_t)row * KTOT + c * 32 + seg * 8);
            }
        }
    };
    auto sts_tile = [&](int b) {
        uint32_t* Ash = sm + b * BUF;
        uint32_t* Asl = Ash + AW;
        uint32_t* Bsh = Asl + AW;
        uint32_t* Bsl = Bsh + BW;
        int base = srow * SMW + sseg * 4;
#pragma unroll
        for (int j = 0; j < 4; j++) {
            uint32_t hi, lo;
            split2(fa[2 * j], fa[2 * j + 1], hi, lo);
            Ash[base + j] = hi;
            Asl[base + j] = lo;
        }
#pragma unroll
        for (int j = 0; j < BCNT; j++) {
            int u = tid + j * 256;
            if (u < BN * 4) {
                int row = u >> 2, seg = u & 3;
                *(uint4*)&Bsh[row * SMW + seg * 4] = bhv[j];
                *(uint4*)&Bsl[row * SMW + seg * 4] = blv[j];
            }
        }
    };

    ldg_tile(0);
    sts_tile(0);
    __syncthreads();

    for (int c = 0; c < KCH; c++) {
        if (c + 1 < KCH) ldg_tile(c + 1);

        uint32_t* Ash = sm + (c & 1) * BUF;
        uint32_t* Asl = Ash + AW;
        uint32_t* Bsh = Asl + AW;
        uint32_t* Bsl = Bsh + BW;
#pragma unroll
        for (int ks = 0; ks < 2; ks++) {
            uint32_t ah[2][4], al[2][4];
#pragma unroll
            for (int mt = 0; mt < 2; mt++) {
                int base = (warp_m * 32 + mt * 16 + g) * SMW + ks * 8;
                ah[mt][0] = Ash[base + q];
                ah[mt][1] = Ash[base + 8 * SMW + q];
                ah[mt][2] = Ash[base + q + 4];
                ah[mt][3] = Ash[base + 8 * SMW + q + 4];
                al[mt][0] = Asl[base + q];
                al[mt][1] = Asl[base + 8 * SMW + q];
                al[mt][2] = Asl[base + q + 4];
                al[mt][3] = Asl[base + 8 * SMW + q + 4];
            }
#pragma unroll
            for (int nt = 0; nt < NT; nt++) {
                int base = (warp_n * (BN / 4) + nt * 8 + g) * SMW + ks * 8;
                uint32_t bh2[2], bl2[2];
                bh2[0] = Bsh[base + q]; bh2[1] = Bsh[base + q + 4];
                bl2[0] = Bsl[base + q]; bl2[1] = Bsl[base + q + 4];
#pragma unroll
                for (int mt = 0; mt < 2; mt++) {
                    mma16816(acc[mt][nt], ah[mt], bh2);
                    mma16816(acc[mt][nt], ah[mt], bl2);
                    mma16816(acc[mt][nt], al[mt], bh2);
                }
            }
        }
        if (c + 1 < KCH) {
            sts_tile((c + 1) & 1);
            __syncthreads();
        }
    }

    // epilogue
#pragma unroll
    for (int mt = 0; mt < 2; mt++) {
        int r0 = row0 + warp_m * 32 + mt * 16 + g;
#pragma unroll
        for (int nt = 0; nt < NT; nt++) {
            int cb = warp_n * (BN / 4) + nt * 8 + q * 2;
            float v0 = acc[mt][nt][0], v1 = acc[mt][nt][1];
            float v2 = acc[mt][nt][2], v3 = acc[mt][nt][3];
            if (MODE == 1) {
                float b0 = __ldg(&bias[cb]), b1v = __ldg(&bias[cb + 1]);
                v0 = fmaxf(v0 + b0, 0.f); v1 = fmaxf(v1 + b1v, 0.f);
                v2 = fmaxf(v2 + b0, 0.f); v3 = fmaxf(v3 + b1v, 0.f);
                if (r0 < N_NODES)     *(float2*)(C + (size_t)r0 * K2 + cb) = make_float2(v0, v1);
                if (r0 + 8 < N_NODES) *(float2*)(C + (size_t)(r0 + 8) * K2 + cb) = make_float2(v2, v3);
            } else {
                if (cb < 128) {
                    if (r0 < N_NODES)     *(float2*)(C + (size_t)r0 * 128 + cb) = make_float2(v0, v1);
                    if (r0 + 8 < N_NODES) *(float2*)(C + (size_t)(r0 + 8) * 128 + cb) = make_float2(v2, v3);
                } else {
                    int oc = cb - 128;
                    float b0 = __ldg(&bias[oc]), b1v = __ldg(&bias[oc + 1]);
                    v0 += b0; v1 += b1v; v2 += b0; v3 += b1v;
                    if (r0 < N_NODES)     *(float2*)(C2 + (size_t)r0 * 128 + oc) = make_float2(v0, v1);
                    if (r0 + 8 < N_NODES) *(float2*)(C2 + (size_t)(r0 + 8) * 128 + oc) = make_float2(v2, v3);
                }
            }
        }
    }
}

// ---------------- launch --------------------------------------------------------
extern "C" void kernel_launch(void* const* d_in, const int* in_sizes, int n_in,
                              void* d_out, int out_size) {
    const float* x   = (const float*)d_in[0];
    const int*   src = (const int*)d_in[1];
    const int*   dst = (const int*)d_in[2];
    const float* Ws1 = (const float*)d_in[3];
    const float* Wn1 = (const float*)d_in[4];
    const float* b1  = (const float*)d_in[5];
    const float* Ws2 = (const float*)d_in[6];
    const float* Wn2 = (const float*)d_in[7];
    const float* b2  = (const float*)d_in[8];
    float* out = (float*)d_out;

    float *p_agg1n, *p_h1, *p_t2, *p_b1p;
    __nv_bfloat16 *p_W1hi, *p_W1lo, *p_Bchi, *p_Bclo;
    cudaGetSymbolAddress((void**)&p_agg1n, g_agg1n);
    cudaGetSymbolAddress((void**)&p_h1,    g_h1);
    cudaGetSymbolAddress((void**)&p_t2,    g_t2);
    cudaGetSymbolAddress((void**)&p_b1p,   g_b1p);
    cudaGetSymbolAddress((void**)&p_W1hi,  g_W1hi);
    cudaGetSymbolAddress((void**)&p_W1lo,  g_W1lo);
    cudaGetSymbolAddress((void**)&p_Bchi,  g_Bchi);
    cudaGetSymbolAddress((void**)&p_Bclo,  g_Bclo);

    constexpr int SMEM1 = 2 * (2 * 64 * SMW + 2 * 160 * SMW) * 4;  // 71680
    constexpr int SMEM2 = 2 * (2 * 64 * SMW + 2 * 256 * SMW) * 4;  // 102400
    cudaFuncSetAttribute(mma_gemm<1>, cudaFuncAttributeMaxDynamicSharedMemorySize, SMEM1);
    cudaFuncSetAttribute(mma_gemm<2>, cudaFuncAttributeMaxDynamicSharedMemorySize, SMEM2);

    const int MB = (N_NODES + 63) / 64;   // 1563

    // CSR build
    zero_cnt<<<98, 256>>>();
    prep_weights<<<192, 256>>>(Ws1, Wn1, Ws2, Wn2, b1);
    hist_kernel<<<N_EDGES / 256, 256>>>(dst);
    scan1_kernel<<<NB, 256>>>();
    scan2_kernel<<<1, 512>>>();
    scan3_kernel<<<NB, 256>>>();
    fill_kernel<<<N_EDGES / 256, 256>>>(src, dst);

    // layer 1
    gather128<0, 0><<<1184, 256>>>(x, p_agg1n);
    mma_gemm<1><<<MB, 256, SMEM1>>>(x, p_agg1n, p_W1hi, p_W1lo, p_b1p, p_h1, nullptr);

    // layer 2 (fused): t2 = h1@Wn2 ; out = h1@Ws2 + b2
    mma_gemm<2><<<MB, 256, SMEM2>>>(p_h1, nullptr, p_Bchi, p_Bclo, b2, p_t2, out);

    // out += deginv * gather(t2)
    gather128<1, 1><<<1184, 256>>>(p_t2, out);
}

// round 7
// speedup vs baseline: 2.4793x; 1.0925x over previous
#include <cuda_runtime.h>
#include <cuda_bf16.h>
#include <cstdint>
#include <cstddef>

#define N_NODES 100000
#define N_EDGES 1600000
#define F_IN    128
#define HID     150
#define K1      256      // layer1 K: 128 self + 128 neigh
#define K2      160      // layer2 K: 150 padded to 160
#define N1      160      // layer1 out cols: 150 padded to 160
#define N_OUT   128
#define NB      391      // ceil(N_NODES/256)

// ---------------- scratch (static device globals) ----------------------------
__device__ __align__(16) int g_cnt[N_NODES];
__device__ __align__(16) int g_excl[N_NODES];
__device__ __align__(16) int g_bsum[512];
__device__ __align__(16) int g_rowptr[N_NODES + 1];
__device__ __align__(16) int g_cur[N_NODES];
__device__ __align__(16) int g_col[N_EDGES];
__device__ __align__(16) int g_wq[2];
__device__ __align__(16) float g_agg1n[(size_t)N_NODES * F_IN];   // deginv-scaled
__device__ __align__(16) float g_h1[(size_t)N_NODES * K2];
__device__ __align__(16) float g_t2[(size_t)N_NODES * N_OUT];
// fragment-order weights: [chunk][ntile][lane][4 words], hi/lo split
__device__ __align__(16) uint32_t g_Bf1hi[8 * 20 * 128];   // W1: KCH=8, NT=20
__device__ __align__(16) uint32_t g_Bf1lo[8 * 20 * 128];
__device__ __align__(16) uint32_t g_Bf2hi[5 * 32 * 128];   // [Wn2|Ws2]: KCH=5, NT=32
__device__ __align__(16) uint32_t g_Bf2lo[5 * 32 * 128];
__device__ __align__(16) float g_b1p[N1];

// ---------------- helpers ------------------------------------------------------
__device__ __forceinline__ void split_bf16(float v, __nv_bfloat16& h, __nv_bfloat16& l) {
    h = __float2bfloat16_rn(v);
    l = __float2bfloat16_rn(v - __bfloat162float(h));
}
__device__ __forceinline__ void split2(float v0, float v1, uint32_t& hi, uint32_t& lo) {
    __nv_bfloat16 h0, l0, h1, l1;
    split_bf16(v0, h0, l0);
    split_bf16(v1, h1, l1);
    hi = (uint32_t)__bfloat16_as_ushort(h0) | ((uint32_t)__bfloat16_as_ushort(h1) << 16);
    lo = (uint32_t)__bfloat16_as_ushort(l0) | ((uint32_t)__bfloat16_as_ushort(l1) << 16);
}
__device__ __forceinline__ void mma16816(float* d, const uint32_t* a, const uint32_t* b) {
    asm volatile(
        "mma.sync.aligned.m16n8k16.row.col.f32.bf16.bf16.f32 "
        "{%0,%1,%2,%3}, {%4,%5,%6,%7}, {%8,%9}, {%0,%1,%2,%3};"
        : "+f"(d[0]), "+f"(d[1]), "+f"(d[2]), "+f"(d[3])
        : "r"(a[0]), "r"(a[1]), "r"(a[2]), "r"(a[3]), "r"(b[0]), "r"(b[1]));
}
// bf16 element index inside a fragment-order B buffer for element (n, k)
__device__ __forceinline__ size_t fragIdx(int n, int k, int NT_TOT) {
    int c = k >> 5, kk = k & 31, w = kk >> 1, b = kk & 1;
    int ks = w >> 3, wq = w & 7, q = wq & 3, ch = wq >> 2;
    int slot = ks * 2 + ch;
    int nt = n >> 3, g = n & 7;
    int lane = g * 4 + q;
    int wi = ((c * NT_TOT + nt) * 32 + lane) * 4 + slot;
    return (size_t)wi * 2 + b;
}

// ---------------- prep: zero counters + fragment-order weights -----------------
__global__ void prep_all(const float* __restrict__ Ws1,
                         const float* __restrict__ Wn1,
                         const float* __restrict__ Ws2,
                         const float* __restrict__ Wn2,
                         const float* __restrict__ b1) {
    int i = blockIdx.x * blockDim.x + threadIdx.x;  // 40960 threads
    if (i < 40960) {
        {   // W1 (transposed, padded): n = out col, k contiguous
            int n = i >> 8, k = i & 255;
            float w = 0.f;
            if (n < HID) w = (k < F_IN) ? Ws1[k * HID + n] : Wn1[(k - F_IN) * HID + n];
            __nv_bfloat16 h, l;
            split_bf16(w, h, l);
            size_t fi = fragIdx(n, k, 20);
            ((__nv_bfloat16*)g_Bf1hi)[fi] = h;
            ((__nv_bfloat16*)g_Bf1lo)[fi] = l;
        }
        {   // [Wn2 | Ws2] concat: rows 0..127 = Wn2 cols, 128..255 = Ws2 cols
            int n = i / 160, k = i % 160;
            float w = 0.f;
            if (k < HID) w = (n < 128) ? Wn2[k * N_OUT + n] : Ws2[k * N_OUT + (n - 128)];
            __nv_bfloat16 h, l;
            split_bf16(w, h, l);
            size_t fi = fragIdx(n, k, 32);
            ((__nv_bfloat16*)g_Bf2hi)[fi] = h;
            ((__nv_bfloat16*)g_Bf2lo)[fi] = l;
        }
    }
    if (i < N_NODES / 4) ((int4*)g_cnt)[i] = make_int4(0, 0, 0, 0);
    if (i < 2) g_wq[i] = 0;
    if (i < N1) g_b1p[i] = (i < HID) ? b1[i] : 0.f;
}

// ---------------- CSR build ----------------------------------------------------
__global__ void hist_kernel(const int* __restrict__ dst) {
    int e = blockIdx.x * blockDim.x + threadIdx.x;
    if (e < N_EDGES) atomicAdd(&g_cnt[dst[e]], 1);
}
__global__ void scan1_kernel() {
    __shared__ int sh[256];
    int tid = threadIdx.x;
    int i = blockIdx.x * 256 + tid;
    int v = (i < N_NODES) ? g_cnt[i] : 0;
    sh[tid] = v;
    __syncthreads();
#pragma unroll
    for (int off = 1; off < 256; off <<= 1) {
        int t = (tid >= off) ? sh[tid - off] : 0;
        __syncthreads();
        sh[tid] += t;
        __syncthreads();
    }
    if (i < N_NODES) g_excl[i] = sh[tid] - v;
    if (tid == 255) g_bsum[blockIdx.x] = sh[255];
}
__global__ void scan23_kernel() {
    __shared__ int sh[256];
    int bid = blockIdx.x, tid = threadIdx.x;
    int s = 0;
    for (int t = tid; t < bid; t += 256) s += g_bsum[t];
    sh[tid] = s;
    __syncthreads();
#pragma unroll
    for (int off = 128; off > 0; off >>= 1) {
        if (tid < off) sh[tid] += sh[tid + off];
        __syncthreads();
    }
    int boff = sh[0];
    int i = bid * 256 + tid;
    if (i < N_NODES) {
        int r = g_excl[i] + boff;
        g_rowptr[i] = r;
        g_cur[i] = r;
    }
    if (bid == 0 && tid == 0) g_rowptr[N_NODES] = N_EDGES;
}
__global__ void fill_kernel(const int* __restrict__ src, const int* __restrict__ dst) {
    int e = blockIdx.x * blockDim.x + threadIdx.x;
    if (e < N_EDGES) {
        int pos = atomicAdd(&g_cur[dst[e]], 1);
        g_col[pos] = src[e];
    }
}

// ---------------- gather: persistent warps + work stealing --------------------
template <int FUSE, int QID>
__global__ void __launch_bounds__(256) gather128(const float* __restrict__ feat,
                                                 float* __restrict__ outp) {
    int lane = threadIdx.x & 31;
    const float4* f4 = (const float4*)feat;
    while (true) {
        int base = 0;
        if (lane == 0) base = atomicAdd(&g_wq[QID], 4);
        base = __shfl_sync(0xffffffffu, base, 0);
        if (base >= N_NODES) break;
        int vend = (base + 4 < N_NODES) ? base + 4 : N_NODES;
        for (int v = base; v < vend; v++) {
            int beg = __ldg(&g_rowptr[v]), end = __ldg(&g_rowptr[v + 1]);
            float4 acc = make_float4(0.f, 0.f, 0.f, 0.f);
            int e = beg;
            for (; e + 4 <= end; e += 4) {
                int s0 = __ldg(&g_col[e]), s1 = __ldg(&g_col[e + 1]);
                int s2 = __ldg(&g_col[e + 2]), s3 = __ldg(&g_col[e + 3]);
                float4 a = __ldg(f4 + (size_t)s0 * 32 + lane);
                float4 b = __ldg(f4 + (size_t)s1 * 32 + lane);
                float4 c = __ldg(f4 + (size_t)s2 * 32 + lane);
                float4 d = __ldg(f4 + (size_t)s3 * 32 + lane);
                acc.x += (a.x + b.x) + (c.x + d.x);
                acc.y += (a.y + b.y) + (c.y + d.y);
                acc.z += (a.z + b.z) + (c.z + d.z);
                acc.w += (a.w + b.w) + (c.w + d.w);
            }
            for (; e < end; e++) {
                int s = __ldg(&g_col[e]);
                float4 a = __ldg(f4 + (size_t)s * 32 + lane);
                acc.x += a.x; acc.y += a.y; acc.z += a.z; acc.w += a.w;
            }
            float dv = (end > beg) ? (1.f / (float)(end - beg)) : 0.f;
            size_t o = (size_t)v * 32 + lane;
            if (FUSE) {
                float4 cur = ((float4*)outp)[o];
                cur.x += dv * acc.x; cur.y += dv * acc.y;
                cur.z += dv * acc.z; cur.w += dv * acc.w;
                ((float4*)outp)[o] = cur;
            } else {
                acc.x *= dv; acc.y *= dv; acc.z *= dv; acc.w *= dv;
                ((float4*)outp)[o] = acc;
            }
        }
    }
}

// ---------------- mma.sync split-bf16 GEMM, fragment-order smem ----------------
// BM=64, BN full width. 8 warps (2 m x 4 n). C = sum_k A[m][k]*B[n][k].
// Smem per buffer: A hi (1024 w) | A lo (1024 w) | B hi (CHW) | B lo (CHW).
// A stored in mma-fragment order with XOR lane swizzle; B copied verbatim from
// pre-arranged fragment-order global. All fragment reads are LDS.128.
// MODE 1: A = [x | agg1n] (K=256), h1 = relu(C + b1p), BN=160
// MODE 2: A = h1 (K=160), B = [Wn2|Ws2] (BN=256):
//         cols<128 -> t2 = C ; cols>=128 -> out = C + b2
template <int MODE>
__global__ void __launch_bounds__(256, 1)
mma_gemm(const float* __restrict__ A, const float* __restrict__ A2,
         const uint4* __restrict__ Bhi, const uint4* __restrict__ Blo,
         const float* __restrict__ bias, float* __restrict__ C, float* __restrict__ C2) {
    constexpr int BN    = (MODE == 1) ? 160 : 256;
    constexpr int KCH   = (MODE == 1) ? 8 : 5;
    constexpr int NTT   = BN / 8;            // n-tiles total
    constexpr int NTW   = BN / 32;           // n-tiles per warp
    constexpr int CHW   = NTT * 128;         // B chunk words per hi
    constexpr int BUFW  = 2048 + 2 * CHW;
    constexpr int BPASS = (NTT * 32 + 255) / 256;

    extern __shared__ uint32_t sm[];
    int tid = threadIdx.x, wid = tid >> 5, lid = tid & 31;
    int warp_m = wid & 1, warp_n = wid >> 1;
    int g = lid >> 2, q = lid & 3;
    int permlid = lid ^ ((lid >> 3) & 3);
    int row0 = blockIdx.x * 64;

    float acc[2][NTW][4];
#pragma unroll
    for (int mt = 0; mt < 2; mt++)
#pragma unroll
        for (int nt = 0; nt < NTW; nt++)
#pragma unroll
            for (int r = 0; r < 4; r++) acc[mt][nt][r] = 0.f;

    int srow = tid >> 2, sseg = tid & 3;
    int grow = row0 + srow;
    int t_w = srow >> 4, rr = srow & 15, gw = rr & 7, rowhalf = rr >> 3;

    float fa[8];
    uint4 bhv[BPASS], blv[BPASS];

    auto ldg_tile = [&](int c) {
#pragma unroll
        for (int j = 0; j < 8; j++) fa[j] = 0.f;
        if (grow < N_NODES) {
            const float* sp;
            if (MODE == 1)
                sp = (c < 4) ? (A + (size_t)grow * 128 + c * 32)
                             : (A2 + (size_t)grow * 128 + (c - 4) * 32);
            else
                sp = A + (size_t)grow * K2 + c * 32;
            float4 p0 = *(const float4*)(sp + sseg * 8);
            float4 p1 = *(const float4*)(sp + sseg * 8 + 4);
            fa[0] = p0.x; fa[1] = p0.y; fa[2] = p0.z; fa[3] = p0.w;
            fa[4] = p1.x; fa[5] = p1.y; fa[6] = p1.z; fa[7] = p1.w;
        }
#pragma unroll
        for (int p = 0; p < BPASS; p++) {
            int u = tid + p * 256;
            if (u < NTT * 32) {
                bhv[p] = Bhi[c * (NTT * 32) + u];
                blv[p] = Blo[c * (NTT * 32) + u];
            }
        }
    };
    auto sts_tile = [&](int b) {
        uint32_t* base = sm + b * BUFW;
#pragma unroll
        for (int j = 0; j < 4; j++) {
            int w = sseg * 4 + j;
            int ks = w >> 3, wq = w & 7, qf = wq & 3, ch = wq >> 2;
            int slot = rowhalf + 2 * ch;
            int lane = gw * 4 + qf;
            int lp = lane ^ ((lane >> 3) & 3);
            int idx = ((t_w * 2 + ks) * 32 + lp) * 4 + slot;
            uint32_t hi, lo;
            split2(fa[2 * j], fa[2 * j + 1], hi, lo);
            base[idx] = hi;
            base[1024 + idx] = lo;
        }
        uint4* Bh4 = (uint4*)(base + 2048);
        uint4* Bl4 = (uint4*)(base + 2048 + CHW);
#pragma unroll
        for (int p = 0; p < BPASS; p++) {
            int u = tid + p * 256;
            if (u < NTT * 32) {
                Bh4[u] = bhv[p];
                Bl4[u] = blv[p];
            }
        }
    };

    ldg_tile(0);
    sts_tile(0);
    __syncthreads();

    for (int c = 0; c < KCH; c++) {
        if (c + 1 < KCH) ldg_tile(c + 1);

        uint32_t* base = sm + (c & 1) * BUFW;
        uint4 AH[2][2], AL[2][2];   // [mt][ks]
#pragma unroll
        for (int mt = 0; mt < 2; mt++)
#pragma unroll
            for (int ks = 0; ks < 2; ks++) {
                int t = warp_m * 2 + mt;
                int idx = ((t * 2 + ks) * 32 + permlid) * 4;
                AH[mt][ks] = *(const uint4*)(base + idx);
                AL[mt][ks] = *(const uint4*)(base + 1024 + idx);
            }
#pragma unroll
        for (int nt = 0; nt < NTW; nt++) {
            int unit = (warp_n * NTW + nt) * 32 + lid;
            uint4 BH = *(const uint4*)(base + 2048 + unit * 4);
            uint4 BL = *(const uint4*)(base + 2048 + CHW + unit * 4);
            const uint32_t* bhw = (const uint32_t*)&BH;
            const uint32_t* blw = (const uint32_t*)&BL;
#pragma unroll
            for (int ks = 0; ks < 2; ks++) {
                uint32_t b2h[2] = {bhw[ks * 2], bhw[ks * 2 + 1]};
                uint32_t b2l[2] = {blw[ks * 2], blw[ks * 2 + 1]};
#pragma unroll
                for (int mt = 0; mt < 2; mt++) {
                    mma16816(acc[mt][nt], (const uint32_t*)&AH[mt][ks], b2h);
                    mma16816(acc[mt][nt], (const uint32_t*)&AH[mt][ks], b2l);
                    mma16816(acc[mt][nt], (const uint32_t*)&AL[mt][ks], b2h);
                }
            }
        }
        if (c + 1 < KCH) {
            sts_tile((c + 1) & 1);
            __syncthreads();
        }
    }

    // epilogue
#pragma unroll
    for (int mt = 0; mt < 2; mt++) {
        int r0 = row0 + warp_m * 32 + mt * 16 + g;
#pragma unroll
        for (int nt = 0; nt < NTW; nt++) {
            int cb = warp_n * (BN / 4) + nt * 8 + q * 2;
            float v0 = acc[mt][nt][0], v1 = acc[mt][nt][1];
            float v2 = acc[mt][nt][2], v3 = acc[mt][nt][3];
            if (MODE == 1) {
                float b0 = __ldg(&bias[cb]), b1v = __ldg(&bias[cb + 1]);
                v0 = fmaxf(v0 + b0, 0.f); v1 = fmaxf(v1 + b1v, 0.f);
                v2 = fmaxf(v2 + b0, 0.f); v3 = fmaxf(v3 + b1v, 0.f);
                if (r0 < N_NODES)     *(float2*)(C + (size_t)r0 * K2 + cb) = make_float2(v0, v1);
                if (r0 + 8 < N_NODES) *(float2*)(C + (size_t)(r0 + 8) * K2 + cb) = make_float2(v2, v3);
            } else {
                if (cb < 128) {
                    if (r0 < N_NODES)     *(float2*)(C + (size_t)r0 * 128 + cb) = make_float2(v0, v1);
                    if (r0 + 8 < N_NODES) *(float2*)(C + (size_t)(r0 + 8) * 128 + cb) = make_float2(v2, v3);
                } else {
                    int oc = cb - 128;
                    float b0 = __ldg(&bias[oc]), b1v = __ldg(&bias[oc + 1]);
                    v0 += b0; v1 += b1v; v2 += b0; v3 += b1v;
                    if (r0 < N_NODES)     *(float2*)(C2 + (size_t)r0 * 128 + oc) = make_float2(v0, v1);
                    if (r0 + 8 < N_NODES) *(float2*)(C2 + (size_t)(r0 + 8) * 128 + oc) = make_float2(v2, v3);
                }
            }
        }
    }
}

// ---------------- launch --------------------------------------------------------
extern "C" void kernel_launch(void* const* d_in, const int* in_sizes, int n_in,
                              void* d_out, int out_size) {
    const float* x   = (const float*)d_in[0];
    const int*   src = (const int*)d_in[1];
    const int*   dst = (const int*)d_in[2];
    const float* Ws1 = (const float*)d_in[3];
    const float* Wn1 = (const float*)d_in[4];
    const float* b1  = (const float*)d_in[5];
    const float* Ws2 = (const float*)d_in[6];
    const float* Wn2 = (const float*)d_in[7];
    const float* b2  = (const float*)d_in[8];
    float* out = (float*)d_out;

    float *p_agg1n, *p_h1, *p_t2, *p_b1p;
    uint32_t *p_B1hi, *p_B1lo, *p_B2hi, *p_B2lo;
    cudaGetSymbolAddress((void**)&p_agg1n, g_agg1n);
    cudaGetSymbolAddress((void**)&p_h1,    g_h1);
    cudaGetSymbolAddress((void**)&p_t2,    g_t2);
    cudaGetSymbolAddress((void**)&p_b1p,   g_b1p);
    cudaGetSymbolAddress((void**)&p_B1hi,  g_Bf1hi);
    cudaGetSymbolAddress((void**)&p_B1lo,  g_Bf1lo);
    cudaGetSymbolAddress((void**)&p_B2hi,  g_Bf2hi);
    cudaGetSymbolAddress((void**)&p_B2lo,  g_Bf2lo);

    constexpr int SMEM1 = 2 * (2048 + 2 * 20 * 128) * 4;   // 57344
    constexpr int SMEM2 = 2 * (2048 + 2 * 32 * 128) * 4;   // 81920
    cudaFuncSetAttribute(mma_gemm<1>, cudaFuncAttributeMaxDynamicSharedMemorySize, SMEM1);
    cudaFuncSetAttribute(mma_gemm<2>, cudaFuncAttributeMaxDynamicSharedMemorySize, SMEM2);

    const int MB = (N_NODES + 63) / 64;   // 1563

    // prep (zero counters + fragment-order weights) then CSR build
    prep_all<<<160, 256>>>(Ws1, Wn1, Ws2, Wn2, b1);
    hist_kernel<<<N_EDGES / 256, 256>>>(dst);
    scan1_kernel<<<NB, 256>>>();
    scan23_kernel<<<NB, 256>>>();
    fill_kernel<<<N_EDGES / 256, 256>>>(src, dst);

    // layer 1
    gather128<0, 0><<<1184, 256>>>(x, p_agg1n);
    mma_gemm<1><<<MB, 256, SMEM1>>>(x, p_agg1n, (const uint4*)p_B1hi, (const uint4*)p_B1lo,
                                    p_b1p, p_h1, nullptr);

    // layer 2 (fused): t2 = h1@Wn2 ; out = h1@Ws2 + b2
    mma_gemm<2><<<MB, 256, SMEM2>>>(p_h1, nullptr, (const uint4*)p_B2hi, (const uint4*)p_B2lo,
                                    b2, p_t2, out);

    // out += deginv * gather(t2)
    gather128<1, 1><<<1184, 256>>>(p_t2, out);
}